// round 1
// baseline (speedup 1.0000x reference)
#include <cuda_runtime.h>
#include <math.h>

// Problem constants (fixed for MLP_21500606284006)
#define Ntok 1024
#define Dm   2048
#define Fm   5632
#define Em   8
#define Rm   16
#define TOPK 2
#define LSCALE 2.0f

// ---------------- device scratch (no allocations allowed) ----------------
__device__ float g_base1[Ntok * Fm];            // x @ W1^T
__device__ float g_base3[Ntok * Fm];            // x @ W3^T
__device__ float g_smix [Ntok * Fm];            // routed mixture
__device__ float g_l13  [Ntok * TOPK * 32];     // per (n,k): [0:16]=l1, [16:32]=l3
__device__ float g_l2w  [Ntok * TOPK * Rm];     // l2 * w * LORA_SCALE
__device__ int   g_topi [Ntok * TOPK];
__device__ float g_topw [Ntok * TOPK];

// ---------------- router: logits, softmax, top-2, renorm ----------------
__global__ void gate_kernel(const float* __restrict__ x,
                            const float* __restrict__ gw,
                            float* __restrict__ logits_out) {
    int n = blockIdx.x;
    int tid = threadIdx.x;          // 256 threads
    __shared__ float sx[Dm];
    for (int i = tid; i < Dm; i += 256) sx[i] = x[(size_t)n * Dm + i];
    __syncthreads();
    int w = tid >> 5, lane = tid & 31;   // 8 warps = 8 experts
    const float* g = gw + (size_t)w * Dm;
    float sum = 0.f;
    for (int d = lane; d < Dm; d += 32) sum += sx[d] * g[d];
    #pragma unroll
    for (int o = 16; o; o >>= 1) sum += __shfl_down_sync(0xffffffffu, sum, o);
    __shared__ float slog[Em];
    if (lane == 0) slog[w] = sum;
    __syncthreads();
    if (tid == 0) {
        float mx = slog[0];
        #pragma unroll
        for (int e = 1; e < Em; e++) mx = fmaxf(mx, slog[e]);
        float p[Em], Z = 0.f;
        #pragma unroll
        for (int e = 0; e < Em; e++) { p[e] = expf(slog[e] - mx); Z += p[e]; }
        #pragma unroll
        for (int e = 0; e < Em; e++) p[e] /= Z;
        int i0 = 0;
        #pragma unroll
        for (int e = 1; e < Em; e++) if (p[e] > p[i0]) i0 = e;   // lowest index wins ties
        int i1 = (i0 == 0) ? 1 : 0;
        #pragma unroll
        for (int e = 0; e < Em; e++) { if (e == i0 || e == i1) continue; if (p[e] > p[i1]) i1 = e; }
        float w0 = p[i0], w1 = p[i1], s = w0 + w1;
        g_topi[n * 2 + 0] = i0; g_topi[n * 2 + 1] = i1;
        g_topw[n * 2 + 0] = w0 / s; g_topw[n * 2 + 1] = w1 / s;
        #pragma unroll
        for (int e = 0; e < Em; e++) logits_out[(size_t)n * Em + e] = slog[e];
    }
}

// ------------- LoRA down-projections l1,l3 for selected experts ----------
__global__ void lora_in_kernel(const float* __restrict__ x,
                               const float* __restrict__ A1,
                               const float* __restrict__ A3) {
    int n = blockIdx.x;
    int tid = threadIdx.x;          // 256
    __shared__ float sx[Dm];
    for (int i = tid; i < Dm; i += 256) sx[i] = x[(size_t)n * Dm + i];
    __syncthreads();
    int w = tid >> 5, lane = tid & 31;
    #pragma unroll
    for (int j = 0; j < 8; j++) {
        int dot = w * 8 + j;        // 0..63
        int k = dot >> 5;           // expert slot
        int rr = dot & 31;          // 0..15 -> l1, 16..31 -> l3
        int e = g_topi[n * 2 + k];
        const float* Arow = (rr < 16 ? A1 : A3) + ((size_t)e * Rm + (rr & 15)) * Dm;
        float sum = 0.f;
        for (int d = lane; d < Dm; d += 32) sum += sx[d] * Arow[d];
        #pragma unroll
        for (int o = 16; o; o >>= 1) sum += __shfl_down_sync(0xffffffffu, sum, o);
        if (lane == 0) g_l13[(size_t)(n * 2 + k) * 32 + rr] = sum;
    }
}

// ---------------- fp32 NT SGEMM: C[M,N] = A[M,K] * B[N,K]^T --------------
__global__ __launch_bounds__(256, 2)
void sgemm_nt(const float* __restrict__ A, const float* __restrict__ B,
              float* __restrict__ C, int M, int N, int K) {
    __shared__ float As[2][16][128];
    __shared__ float Bs[2][16][128];
    const int tid = threadIdx.x;
    const int bm = blockIdx.y * 128;
    const int bn = blockIdx.x * 128;
    const int lr = tid >> 2;               // 0..63
    const int lc = (tid & 3) << 2;         // 0,4,8,12
    const float* Ap = A + (size_t)(bm + lr) * K + lc;
    const float* Bp = B + (size_t)(bn + lr) * K + lc;
    const int tx = (tid & 15) << 3;
    const int ty = (tid >> 4) << 3;

    float acc[8][8];
    #pragma unroll
    for (int i = 0; i < 8; i++)
        #pragma unroll
        for (int j = 0; j < 8; j++) acc[i][j] = 0.f;

    {   // prologue: tile 0 -> buffer 0
        float4 a0 = *(const float4*)Ap;
        float4 a1 = *(const float4*)(Ap + (size_t)64 * K);
        float4 b0 = *(const float4*)Bp;
        float4 b1 = *(const float4*)(Bp + (size_t)64 * K);
        As[0][lc+0][lr] = a0.x; As[0][lc+1][lr] = a0.y; As[0][lc+2][lr] = a0.z; As[0][lc+3][lr] = a0.w;
        As[0][lc+0][lr+64] = a1.x; As[0][lc+1][lr+64] = a1.y; As[0][lc+2][lr+64] = a1.z; As[0][lc+3][lr+64] = a1.w;
        Bs[0][lc+0][lr] = b0.x; Bs[0][lc+1][lr] = b0.y; Bs[0][lc+2][lr] = b0.z; Bs[0][lc+3][lr] = b0.w;
        Bs[0][lc+0][lr+64] = b1.x; Bs[0][lc+1][lr+64] = b1.y; Bs[0][lc+2][lr+64] = b1.z; Bs[0][lc+3][lr+64] = b1.w;
    }
    __syncthreads();

    const int nk = K >> 4;
    for (int kt = 0; kt < nk; kt++) {
        const int cur = kt & 1;
        float4 a0, a1, b0, b1;
        const bool more = (kt + 1 < nk);
        if (more) {
            const float* Ap2 = Ap + (kt + 1) * 16;
            const float* Bp2 = Bp + (kt + 1) * 16;
            a0 = *(const float4*)Ap2;
            a1 = *(const float4*)(Ap2 + (size_t)64 * K);
            b0 = *(const float4*)Bp2;
            b1 = *(const float4*)(Bp2 + (size_t)64 * K);
        }
        #pragma unroll
        for (int k = 0; k < 16; k++) {
            float ar[8], br[8];
            *(float4*)&ar[0] = *(const float4*)&As[cur][k][ty];
            *(float4*)&ar[4] = *(const float4*)&As[cur][k][ty + 4];
            *(float4*)&br[0] = *(const float4*)&Bs[cur][k][tx];
            *(float4*)&br[4] = *(const float4*)&Bs[cur][k][tx + 4];
            #pragma unroll
            for (int i = 0; i < 8; i++)
                #pragma unroll
                for (int j = 0; j < 8; j++)
                    acc[i][j] = fmaf(ar[i], br[j], acc[i][j]);
        }
        if (more) {
            const int nxt = cur ^ 1;
            As[nxt][lc+0][lr] = a0.x; As[nxt][lc+1][lr] = a0.y; As[nxt][lc+2][lr] = a0.z; As[nxt][lc+3][lr] = a0.w;
            As[nxt][lc+0][lr+64] = a1.x; As[nxt][lc+1][lr+64] = a1.y; As[nxt][lc+2][lr+64] = a1.z; As[nxt][lc+3][lr+64] = a1.w;
            Bs[nxt][lc+0][lr] = b0.x; Bs[nxt][lc+1][lr] = b0.y; Bs[nxt][lc+2][lr] = b0.z; Bs[nxt][lc+3][lr] = b0.w;
            Bs[nxt][lc+0][lr+64] = b1.x; Bs[nxt][lc+1][lr+64] = b1.y; Bs[nxt][lc+2][lr+64] = b1.z; Bs[nxt][lc+3][lr+64] = b1.w;
            __syncthreads();
        }
    }

    float* Cp = C + (size_t)(bm + ty) * N + bn + tx;
    #pragma unroll
    for (int i = 0; i < 8; i++) {
        float4 v0 = make_float4(acc[i][0], acc[i][1], acc[i][2], acc[i][3]);
        float4 v1 = make_float4(acc[i][4], acc[i][5], acc[i][6], acc[i][7]);
        *(float4*)(Cp + (size_t)i * N)     = v0;
        *(float4*)(Cp + (size_t)i * N + 4) = v1;
    }
}

// --------- fused per-token SwiGLU + routed mix + l2 accumulation ---------
__global__ void swiglu_kernel(const float* __restrict__ B1,
                              const float* __restrict__ B3,
                              const float* __restrict__ A2) {
    int n = blockIdx.x;
    int tid = threadIdx.x;          // 256
    __shared__ float sl[2][32];     // [k][0:16]=l1, [16:32]=l3
    __shared__ int   se[2];
    __shared__ float swt[2];
    if (tid < 64) sl[tid >> 5][tid & 31] = g_l13[(size_t)n * 64 + tid];
    if (tid < 2) { se[tid] = g_topi[n * 2 + tid]; swt[tid] = g_topw[n * 2 + tid]; }
    __syncthreads();

    float l2acc[2][16];
    #pragma unroll
    for (int k = 0; k < 2; k++)
        #pragma unroll
        for (int r = 0; r < 16; r++) l2acc[k][r] = 0.f;

    const float* b1r = g_base1 + (size_t)n * Fm;
    const float* b3r = g_base3 + (size_t)n * Fm;
    float* smixr = g_smix + (size_t)n * Fm;

    for (int f = tid; f < Fm; f += 256) {
        float b1 = b1r[f], b3 = b3r[f];
        float mix = 0.f;
        #pragma unroll
        for (int k = 0; k < 2; k++) {
            int e = se[k];
            const float4* B1p = (const float4*)(B1 + ((size_t)e * Fm + f) * Rm);
            const float4* B3p = (const float4*)(B3 + ((size_t)e * Fm + f) * Rm);
            float h1 = b1, h3 = b3;
            #pragma unroll
            for (int q = 0; q < 4; q++) {
                float4 v1 = B1p[q], v3 = B3p[q];
                h1 += LSCALE * (sl[k][4*q+0]*v1.x + sl[k][4*q+1]*v1.y + sl[k][4*q+2]*v1.z + sl[k][4*q+3]*v1.w);
                h3 += LSCALE * (sl[k][16+4*q+0]*v3.x + sl[k][16+4*q+1]*v3.y + sl[k][16+4*q+2]*v3.z + sl[k][16+4*q+3]*v3.w);
            }
            float sig = 1.f / (1.f + expf(-h1));
            float s = h1 * sig * h3;
            mix += swt[k] * s;
            const float* A2p = A2 + (size_t)e * Rm * Fm + f;
            #pragma unroll
            for (int r = 0; r < 16; r++)
                l2acc[k][r] = fmaf(s, A2p[(size_t)r * Fm], l2acc[k][r]);
        }
        smixr[f] = mix;
    }

    // reduce l2acc across block
    int w = tid >> 5, lane = tid & 31;
    __shared__ float sred[8][32];
    #pragma unroll
    for (int k = 0; k < 2; k++)
        #pragma unroll
        for (int r = 0; r < 16; r++) {
            float v = l2acc[k][r];
            #pragma unroll
            for (int o = 16; o; o >>= 1) v += __shfl_down_sync(0xffffffffu, v, o);
            if (lane == 0) sred[w][k * 16 + r] = v;
        }
    __syncthreads();
    if (tid < 32) {
        float v = 0.f;
        #pragma unroll
        for (int ww = 0; ww < 8; ww++) v += sred[ww][tid];
        int k = tid >> 4;
        g_l2w[(size_t)n * 32 + tid] = v * swt[k] * LSCALE;
    }
}

// --------------- output LoRA: out[n,d] += sum_{k,r} l2w * B2 -------------
__global__ void lora_out_kernel(const float* __restrict__ B2, float* __restrict__ out) {
    int n = blockIdx.y;
    int d = blockIdx.x * 256 + threadIdx.x;
    __shared__ float sl2[32];
    __shared__ int se[2];
    if (threadIdx.x < 32) sl2[threadIdx.x] = g_l2w[(size_t)n * 32 + threadIdx.x];
    if (threadIdx.x < 2) se[threadIdx.x] = g_topi[n * 2 + threadIdx.x];
    __syncthreads();
    float acc = out[(size_t)n * Dm + d];
    #pragma unroll
    for (int k = 0; k < 2; k++) {
        int e = se[k];
        const float4* bp = (const float4*)(B2 + ((size_t)e * Dm + d) * Rm);
        #pragma unroll
        for (int q = 0; q < 4; q++) {
            float4 v = bp[q];
            acc += sl2[k*16+4*q+0]*v.x + sl2[k*16+4*q+1]*v.y + sl2[k*16+4*q+2]*v.z + sl2[k*16+4*q+3]*v.w;
        }
    }
    out[(size_t)n * Dm + d] = acc;
}

// --------------------------------- launch --------------------------------
extern "C" void kernel_launch(void* const* d_in, const int* in_sizes, int n_in,
                              void* d_out, int out_size) {
    const float* x      = (const float*)d_in[0];   // [N, D]
    const float* gate_w = (const float*)d_in[1];   // [E, D]
    const float* W1     = (const float*)d_in[2];   // [F, D]
    const float* W3     = (const float*)d_in[3];   // [F, D]
    const float* W2     = (const float*)d_in[4];   // [D, F]
    const float* A1     = (const float*)d_in[5];   // [E, R, D]
    const float* B1     = (const float*)d_in[6];   // [E, F, R]
    const float* A3     = (const float*)d_in[7];   // [E, R, D]
    const float* B3     = (const float*)d_in[8];   // [E, F, R]
    const float* A2     = (const float*)d_in[9];   // [E, R, F]
    const float* B2     = (const float*)d_in[10];  // [E, D, R]

    float* out    = (float*)d_out;                 // [N, D]
    float* logits = (float*)d_out + (size_t)Ntok * Dm;  // [N, E]

    float *base1, *base3, *smix;
    cudaGetSymbolAddress((void**)&base1, g_base1);
    cudaGetSymbolAddress((void**)&base3, g_base3);
    cudaGetSymbolAddress((void**)&smix,  g_smix);

    // 1) router
    gate_kernel<<<Ntok, 256>>>(x, gate_w, logits);
    // 2) LoRA down-proj for selected experts
    lora_in_kernel<<<Ntok, 256>>>(x, A1, A3);
    // 3) big base GEMMs: base1 = x@W1^T, base3 = x@W3^T
    {
        dim3 grid(Fm / 128, Ntok / 128);
        sgemm_nt<<<grid, 256>>>(x, W1, base1, Ntok, Fm, Dm);
        sgemm_nt<<<grid, 256>>>(x, W3, base3, Ntok, Fm, Dm);
    }
    // 4) fused SwiGLU + mix + l2
    swiglu_kernel<<<Ntok, 256>>>(B1, B3, A2);
    // 5) down-projection GEMM: out = smix @ W2^T
    {
        dim3 grid(Dm / 128, Ntok / 128);
        sgemm_nt<<<grid, 256>>>(smix, W2, out, Ntok, Dm, Fm);
    }
    // 6) output LoRA add
    {
        dim3 grid(Dm / 256, Ntok);
        lora_out_kernel<<<grid, 256>>>(B2, out);
    }
}

// round 3
// speedup vs baseline: 1.6706x; 1.6706x over previous
#include <cuda_runtime.h>
#include <cuda_bf16.h>
#include <math.h>
#include <stdint.h>

#define Ntok 1024
#define Dm   2048
#define Fm   5632
#define Em   8
#define Rm   16
#define LSCALE 2.0f
#define K3D  (3*Dm)   // 6144
#define K3F  (3*Fm)   // 16896
#define NB1  (Fm + 256)   // 5888: W1 rows + 256 LoRA-A rows

// ---------------- device scratch (no allocations allowed) ----------------
__device__ float g_base1[Ntok * NB1];            // [x@W1^T | x@A13^T]
__device__ float g_base3[Ntok * Fm];
__device__ float g_smix [Ntok * Fm];
__device__ float g_l2w  [Ntok * 32];
__device__ int   g_topi [Ntok * 2];
__device__ float g_topw [Ntok * 2];
__device__ __align__(256) __nv_bfloat16 g_xcat[(size_t)Ntok * K3D];
__device__ __align__(256) __nv_bfloat16 g_w1c [(size_t)NB1  * K3D];
__device__ __align__(256) __nv_bfloat16 g_w3c [(size_t)Fm   * K3D];
__device__ __align__(256) __nv_bfloat16 g_w2c [(size_t)Dm   * K3F];
__device__ __align__(256) __nv_bfloat16 g_smc [(size_t)Ntok * K3F];

// ---------------- PTX helpers ----------------
__device__ __forceinline__ uint32_t s2u(const void* p) {
    uint32_t a;
    asm("{ .reg .u64 t; cvta.to.shared.u64 t, %1; cvt.u32.u64 %0, t; }" : "=r"(a) : "l"(p));
    return a;
}
#define CPA16(d, s) asm volatile("cp.async.cg.shared.global [%0], [%1], 16;" :: "r"(d), "l"(s))
#define LDSM4(R0,R1,R2,R3,addr) asm volatile( \
    "ldmatrix.sync.aligned.m8n8.x4.shared.b16 {%0,%1,%2,%3}, [%4];" \
    : "=r"(R0),"=r"(R1),"=r"(R2),"=r"(R3) : "r"(addr))
#define MMA16816(c, a, b0, b1) asm volatile( \
    "mma.sync.aligned.m16n8k16.row.col.f32.bf16.bf16.f32 " \
    "{%0,%1,%2,%3}, {%4,%5,%6,%7}, {%8,%9}, {%0,%1,%2,%3};" \
    : "+f"((c)[0]),"+f"((c)[1]),"+f"((c)[2]),"+f"((c)[3]) \
    : "r"((a)[0]),"r"((a)[1]),"r"((a)[2]),"r"((a)[3]), "r"(b0),"r"(b1))

// ---------------- fp32 -> [hi|hi|lo] (A) or [hi|lo|hi] (B) bf16 split ----------------
__global__ void split_kernel(const float* __restrict__ src, __nv_bfloat16* __restrict__ dst,
                             int K, int total4, int bmode) {
    int t = blockIdx.x * 256 + threadIdx.x;
    if (t >= total4) return;
    size_t idx = (size_t)t * 4;
    int row = (int)(idx / K);
    int col = (int)(idx - (size_t)row * K);
    float4 v = *(const float4*)(src + idx);
    __nv_bfloat16 h0 = __float2bfloat16(v.x), h1 = __float2bfloat16(v.y);
    __nv_bfloat16 h2 = __float2bfloat16(v.z), h3 = __float2bfloat16(v.w);
    __nv_bfloat16 l0 = __float2bfloat16(v.x - __bfloat162float(h0));
    __nv_bfloat16 l1 = __float2bfloat16(v.y - __bfloat162float(h1));
    __nv_bfloat16 l2 = __float2bfloat16(v.z - __bfloat162float(h2));
    __nv_bfloat16 l3 = __float2bfloat16(v.w - __bfloat162float(h3));
    __nv_bfloat162 H0, H1, L0, L1;
    H0.x = h0; H0.y = h1; H1.x = h2; H1.y = h3;
    L0.x = l0; L0.y = l1; L1.x = l2; L1.y = l3;
    __nv_bfloat16* base = dst + (size_t)row * 3 * K + col;
    __nv_bfloat162* s0 = (__nv_bfloat162*)base;
    __nv_bfloat162* s1 = (__nv_bfloat162*)(base + K);
    __nv_bfloat162* s2 = (__nv_bfloat162*)(base + 2 * K);
    s0[0] = H0; s0[1] = H1;
    if (bmode) { s1[0] = L0; s1[1] = L1; s2[0] = H0; s2[1] = H1; }
    else       { s1[0] = H0; s1[1] = H1; s2[0] = L0; s2[1] = L1; }
}

// A13 concat + split (B-mode): rows j = e*32+rr; rr<16 -> A1[e][rr], else A3[e][rr-16]
__global__ void split_a13_kernel(const float* __restrict__ A1, const float* __restrict__ A3,
                                 __nv_bfloat16* __restrict__ dst) {
    int t = blockIdx.x * 256 + threadIdx.x;          // 256*Dm/4 total
    size_t idx = (size_t)t * 4;
    int row = (int)(idx / Dm);
    int col = (int)(idx - (size_t)row * Dm);
    int e = row >> 5, rr = row & 31;
    const float* src = (rr < 16) ? (A1 + ((size_t)e * 16 + rr) * Dm)
                                 : (A3 + ((size_t)e * 16 + (rr - 16)) * Dm);
    float4 v = *(const float4*)(src + col);
    __nv_bfloat16 h0 = __float2bfloat16(v.x), h1 = __float2bfloat16(v.y);
    __nv_bfloat16 h2 = __float2bfloat16(v.z), h3 = __float2bfloat16(v.w);
    __nv_bfloat16 l0 = __float2bfloat16(v.x - __bfloat162float(h0));
    __nv_bfloat16 l1 = __float2bfloat16(v.y - __bfloat162float(h1));
    __nv_bfloat16 l2 = __float2bfloat16(v.z - __bfloat162float(h2));
    __nv_bfloat16 l3 = __float2bfloat16(v.w - __bfloat162float(h3));
    __nv_bfloat162 H0, H1, L0, L1;
    H0.x = h0; H0.y = h1; H1.x = h2; H1.y = h3;
    L0.x = l0; L0.y = l1; L1.x = l2; L1.y = l3;
    __nv_bfloat16* base = dst + (size_t)row * K3D + col;
    ((__nv_bfloat162*)base)[0] = H0;            ((__nv_bfloat162*)base)[1] = H1;
    ((__nv_bfloat162*)(base + Dm))[0] = L0;     ((__nv_bfloat162*)(base + Dm))[1] = L1;
    ((__nv_bfloat162*)(base + 2*Dm))[0] = H0;   ((__nv_bfloat162*)(base + 2*Dm))[1] = H1;
}

// ---------------- HMMA bf16 NT GEMM: C[M,Nn] = A[M,K] @ B[Nn,K]^T ----------------
// 128x128 CTA tile, 8 warps (2x4), warp tile 64x32, BK=32, 4-stage cp.async.
#define NSTAGE      4
#define STAGE_BYTES 10240            // 128 rows * 80B
#define BBUF_OFF    (NSTAGE * STAGE_BYTES)   // 40960
#define GEMM_SMEM   (2 * BBUF_OFF)   // 81920

__global__ void __launch_bounds__(256)
gemm_mma(const __nv_bfloat16* __restrict__ Ag, const __nv_bfloat16* __restrict__ Bg,
         float* __restrict__ Cg, int Nn, int K) {
    extern __shared__ char smraw[];
    const uint32_t sb = s2u(smraw);
    const int tid = threadIdx.x;
    const int lane = tid & 31, wid = tid >> 5;
    const int wm = wid & 1, wn = wid >> 1;
    const int bm = blockIdx.y * 128, bn = blockIdx.x * 128;
    const int nk = K >> 5;

    // global->smem load mapping: thread covers 32B of one row of A and of B
    const int r = tid >> 1, half = tid & 1;
    const __nv_bfloat16* gA = Ag + (size_t)(bm + r) * K + half * 16;
    const __nv_bfloat16* gB = Bg + (size_t)(bn + r) * K + half * 16;
    const uint32_t dA = sb + r * 80 + half * 32;
    const uint32_t dB = sb + BBUF_OFF + r * 80 + half * 32;

    // ldmatrix lane addressing (same pattern for A and B)
    const uint32_t lrow = (uint32_t)(lane & 15);
    const uint32_t lcolb = (uint32_t)(lane >> 4) * 16;
    const uint32_t aLd = sb + (wm * 64 + lrow) * 80 + lcolb;
    const uint32_t bLd = sb + BBUF_OFF + (wn * 32 + lrow) * 80 + lcolb;

    float acc[4][4][4];
    #pragma unroll
    for (int i = 0; i < 4; i++)
        #pragma unroll
        for (int j = 0; j < 4; j++)
            #pragma unroll
            for (int q = 0; q < 4; q++) acc[i][j][q] = 0.f;

    #pragma unroll
    for (int s = 0; s < NSTAGE - 1; s++) {
        const __nv_bfloat16* a = gA + s * 32;
        const __nv_bfloat16* b = gB + s * 32;
        uint32_t so = (uint32_t)s * STAGE_BYTES;
        CPA16(dA + so, a); CPA16(dA + so + 16, a + 8);
        CPA16(dB + so, b); CPA16(dB + so + 16, b + 8);
        asm volatile("cp.async.commit_group;" ::: "memory");
    }

    for (int kt = 0; kt < nk; kt++) {
        int ls = kt + NSTAGE - 1;
        if (ls < nk) {
            uint32_t so = (uint32_t)(ls & (NSTAGE - 1)) * STAGE_BYTES;
            const __nv_bfloat16* a = gA + (size_t)ls * 32;
            const __nv_bfloat16* b = gB + (size_t)ls * 32;
            CPA16(dA + so, a); CPA16(dA + so + 16, a + 8);
            CPA16(dB + so, b); CPA16(dB + so + 16, b + 8);
        }
        asm volatile("cp.async.commit_group;" ::: "memory");
        asm volatile("cp.async.wait_group %0;" :: "n"(NSTAGE - 1) : "memory");
        __syncthreads();

        const uint32_t so = (uint32_t)(kt & (NSTAGE - 1)) * STAGE_BYTES;
        #pragma unroll
        for (int ks = 0; ks < 2; ks++) {
            uint32_t Ar[4][4], Br[2][4];
            #pragma unroll
            for (int mt = 0; mt < 4; mt++)
                LDSM4(Ar[mt][0], Ar[mt][1], Ar[mt][2], Ar[mt][3],
                      aLd + so + mt * 1280 + ks * 32);
            #pragma unroll
            for (int p = 0; p < 2; p++)
                LDSM4(Br[p][0], Br[p][1], Br[p][2], Br[p][3],
                      bLd + so + p * 1280 + ks * 32);
            #pragma unroll
            for (int mt = 0; mt < 4; mt++)
                #pragma unroll
                for (int nt = 0; nt < 4; nt++) {
                    uint32_t b0 = Br[nt >> 1][nt & 1];
                    uint32_t b1 = Br[nt >> 1][2 + (nt & 1)];
                    MMA16816(acc[mt][nt], Ar[mt], b0, b1);
                }
        }
        __syncthreads();
    }

    const int g = lane >> 2, t4 = lane & 3;
    #pragma unroll
    for (int mt = 0; mt < 4; mt++) {
        int row = bm + wm * 64 + mt * 16 + g;
        #pragma unroll
        for (int nt = 0; nt < 4; nt++) {
            int col = bn + wn * 32 + nt * 8 + 2 * t4;
            *(float2*)(Cg + (size_t)row * Nn + col)       = make_float2(acc[mt][nt][0], acc[mt][nt][1]);
            *(float2*)(Cg + (size_t)(row + 8) * Nn + col) = make_float2(acc[mt][nt][2], acc[mt][nt][3]);
        }
    }
}

// ---------------- router: logits, softmax, top-2, renorm ----------------
__global__ void gate_kernel(const float* __restrict__ x,
                            const float* __restrict__ gw,
                            float* __restrict__ logits_out) {
    int n = blockIdx.x;
    int tid = threadIdx.x;
    __shared__ float sx[Dm];
    for (int i = tid; i < Dm; i += 256) sx[i] = x[(size_t)n * Dm + i];
    __syncthreads();
    int w = tid >> 5, lane = tid & 31;
    const float* g = gw + (size_t)w * Dm;
    float sum = 0.f;
    for (int d = lane; d < Dm; d += 32) sum += sx[d] * g[d];
    #pragma unroll
    for (int o = 16; o; o >>= 1) sum += __shfl_down_sync(0xffffffffu, sum, o);
    __shared__ float slog[Em];
    if (lane == 0) slog[w] = sum;
    __syncthreads();
    if (tid == 0) {
        float mx = slog[0];
        #pragma unroll
        for (int e = 1; e < Em; e++) mx = fmaxf(mx, slog[e]);
        float p[Em], Z = 0.f;
        #pragma unroll
        for (int e = 0; e < Em; e++) { p[e] = expf(slog[e] - mx); Z += p[e]; }
        #pragma unroll
        for (int e = 0; e < Em; e++) p[e] /= Z;
        int i0 = 0;
        #pragma unroll
        for (int e = 1; e < Em; e++) if (p[e] > p[i0]) i0 = e;
        int i1 = (i0 == 0) ? 1 : 0;
        #pragma unroll
        for (int e = 0; e < Em; e++) { if (e == i0 || e == i1) continue; if (p[e] > p[i1]) i1 = e; }
        float w0 = p[i0], w1 = p[i1], s = w0 + w1;
        g_topi[n * 2 + 0] = i0; g_topi[n * 2 + 1] = i1;
        g_topw[n * 2 + 0] = w0 / s; g_topw[n * 2 + 1] = w1 / s;
        #pragma unroll
        for (int e = 0; e < Em; e++) logits_out[(size_t)n * Em + e] = slog[e];
    }
}

// --------- fused per-token SwiGLU + routed mix + l2 accumulation ---------
__global__ void swiglu_kernel(const float* __restrict__ B1,
                              const float* __restrict__ B3,
                              const float* __restrict__ A2) {
    int n = blockIdx.x;
    int tid = threadIdx.x;
    __shared__ float sl[2][32];
    __shared__ int   se[2];
    __shared__ float swt[2];
    if (tid < 2) { se[tid] = g_topi[n * 2 + tid]; swt[tid] = g_topw[n * 2 + tid]; }
    __syncthreads();
    if (tid < 64) {
        int k = tid >> 5, rr = tid & 31;
        sl[k][rr] = g_base1[(size_t)n * NB1 + Fm + se[k] * 32 + rr];
    }
    __syncthreads();

    float l2acc[2][16];
    #pragma unroll
    for (int k = 0; k < 2; k++)
        #pragma unroll
        for (int r = 0; r < 16; r++) l2acc[k][r] = 0.f;

    const float* b1r = g_base1 + (size_t)n * NB1;
    const float* b3r = g_base3 + (size_t)n * Fm;
    float* smixr = g_smix + (size_t)n * Fm;

    for (int f = tid; f < Fm; f += 256) {
        float b1 = b1r[f], b3 = b3r[f];
        float mix = 0.f;
        #pragma unroll
        for (int k = 0; k < 2; k++) {
            int e = se[k];
            const float4* B1p = (const float4*)(B1 + ((size_t)e * Fm + f) * Rm);
            const float4* B3p = (const float4*)(B3 + ((size_t)e * Fm + f) * Rm);
            float h1 = b1, h3 = b3;
            #pragma unroll
            for (int q = 0; q < 4; q++) {
                float4 v1 = B1p[q], v3 = B3p[q];
                h1 += LSCALE * (sl[k][4*q+0]*v1.x + sl[k][4*q+1]*v1.y + sl[k][4*q+2]*v1.z + sl[k][4*q+3]*v1.w);
                h3 += LSCALE * (sl[k][16+4*q+0]*v3.x + sl[k][16+4*q+1]*v3.y + sl[k][16+4*q+2]*v3.z + sl[k][16+4*q+3]*v3.w);
            }
            float sig = 1.f / (1.f + expf(-h1));
            float s = h1 * sig * h3;
            mix += swt[k] * s;
            const float* A2p = A2 + (size_t)e * Rm * Fm + f;
            #pragma unroll
            for (int r = 0; r < 16; r++)
                l2acc[k][r] = fmaf(s, A2p[(size_t)r * Fm], l2acc[k][r]);
        }
        smixr[f] = mix;
    }

    int w = tid >> 5, lane = tid & 31;
    __shared__ float sred[8][32];
    #pragma unroll
    for (int k = 0; k < 2; k++)
        #pragma unroll
        for (int r = 0; r < 16; r++) {
            float v = l2acc[k][r];
            #pragma unroll
            for (int o = 16; o; o >>= 1) v += __shfl_down_sync(0xffffffffu, v, o);
            if (lane == 0) sred[w][k * 16 + r] = v;
        }
    __syncthreads();
    if (tid < 32) {
        float v = 0.f;
        #pragma unroll
        for (int ww = 0; ww < 8; ww++) v += sred[ww][tid];
        int k = tid >> 4;
        g_l2w[(size_t)n * 32 + tid] = v * swt[k] * LSCALE;
    }
}

// --------------- output LoRA: out[n,d] += sum_{k,r} l2w * B2 -------------
__global__ void lora_out_kernel(const float* __restrict__ B2, float* __restrict__ out) {
    int n = blockIdx.y;
    int d = blockIdx.x * 256 + threadIdx.x;
    __shared__ float sl2[32];
    __shared__ int se[2];
    if (threadIdx.x < 32) sl2[threadIdx.x] = g_l2w[(size_t)n * 32 + threadIdx.x];
    if (threadIdx.x < 2) se[threadIdx.x] = g_topi[n * 2 + threadIdx.x];
    __syncthreads();
    float acc = out[(size_t)n * Dm + d];
    #pragma unroll
    for (int k = 0; k < 2; k++) {
        int e = se[k];
        const float4* bp = (const float4*)(B2 + ((size_t)e * Dm + d) * Rm);
        #pragma unroll
        for (int q = 0; q < 4; q++) {
            float4 v = bp[q];
            acc += sl2[k*16+4*q+0]*v.x + sl2[k*16+4*q+1]*v.y + sl2[k*16+4*q+2]*v.z + sl2[k*16+4*q+3]*v.w;
        }
    }
    out[(size_t)n * Dm + d] = acc;
}

// --------------------------------- launch --------------------------------
extern "C" void kernel_launch(void* const* d_in, const int* in_sizes, int n_in,
                              void* d_out, int out_size) {
    const float* x      = (const float*)d_in[0];
    const float* gate_w = (const float*)d_in[1];
    const float* W1     = (const float*)d_in[2];
    const float* W3     = (const float*)d_in[3];
    const float* W2     = (const float*)d_in[4];
    const float* A1     = (const float*)d_in[5];
    const float* B1     = (const float*)d_in[6];
    const float* A3     = (const float*)d_in[7];
    const float* B3     = (const float*)d_in[8];
    const float* A2     = (const float*)d_in[9];
    const float* B2     = (const float*)d_in[10];

    float* out    = (float*)d_out;
    float* logits = (float*)d_out + (size_t)Ntok * Dm;

    float *base1, *base3, *smix;
    __nv_bfloat16 *xcat, *w1c, *w3c, *w2c, *smc;
    cudaGetSymbolAddress((void**)&base1, g_base1);
    cudaGetSymbolAddress((void**)&base3, g_base3);
    cudaGetSymbolAddress((void**)&smix,  g_smix);
    cudaGetSymbolAddress((void**)&xcat,  g_xcat);
    cudaGetSymbolAddress((void**)&w1c,   g_w1c);
    cudaGetSymbolAddress((void**)&w3c,   g_w3c);
    cudaGetSymbolAddress((void**)&w2c,   g_w2c);
    cudaGetSymbolAddress((void**)&smc,   g_smc);

    cudaFuncSetAttribute(gemm_mma, cudaFuncAttributeMaxDynamicSharedMemorySize, GEMM_SMEM);

    // conversions (A-mode: hi,hi,lo ; B-mode: hi,lo,hi)
    split_kernel<<<(Ntok * Dm / 4 + 255) / 256, 256>>>(x,  xcat, Dm, Ntok * Dm / 4, 0);
    split_kernel<<<(Fm * Dm / 4 + 255) / 256, 256>>>(W1, w1c, Dm, Fm * Dm / 4, 1);
    split_a13_kernel<<<(256 * Dm / 4) / 256, 256>>>(A1, A3, w1c + (size_t)Fm * K3D);
    split_kernel<<<(Fm * Dm / 4 + 255) / 256, 256>>>(W3, w3c, Dm, Fm * Dm / 4, 1);
    split_kernel<<<(Dm * Fm / 4 + 255) / 256, 256>>>(W2, w2c, Fm, Dm * Fm / 4, 1);

    // router
    gate_kernel<<<Ntok, 256>>>(x, gate_w, logits);

    // base GEMMs (W1 GEMM also computes LoRA-A projections in cols Fm..Fm+255)
    {
        dim3 grid(NB1 / 128, Ntok / 128);   // 46 x 8
        gemm_mma<<<grid, 256, GEMM_SMEM>>>(xcat, w1c, base1, NB1, K3D);
    }
    {
        dim3 grid(Fm / 128, Ntok / 128);    // 44 x 8
        gemm_mma<<<grid, 256, GEMM_SMEM>>>(xcat, w3c, base3, Fm, K3D);
    }
    // fused SwiGLU + mix + l2
    swiglu_kernel<<<Ntok, 256>>>(B1, B3, A2);
    // convert smix, down-projection GEMM -> out
    split_kernel<<<(Ntok * Fm / 4 + 255) / 256, 256>>>(smix, smc, Fm, Ntok * Fm / 4, 0);
    {
        dim3 grid(Dm / 128, Ntok / 128);    // 16 x 8
        gemm_mma<<<grid, 256, GEMM_SMEM>>>(smc, w2c, out, Dm, K3F);
    }
    // output LoRA add
    {
        dim3 grid(Dm / 256, Ntok);
        lora_out_kernel<<<grid, 256>>>(B2, out);
    }
}